// round 4
// baseline (speedup 1.0000x reference)
#include <cuda_runtime.h>
#include <math.h>

// Repacked class boxes. Row = 64 floats (256B, line-aligned).
// f[2k]=lo_k, f[2k+1]=hi_k (k=0..24); f[50]=s; f[51]=b; rest pad.
// loss = b - inter_area * s reproduces the reference's 3-way where().
#define MAX_CLASSES 100000
__device__ float g_rows[(size_t)MAX_CLASSES * 64];
__device__ double g_acc;
__device__ unsigned int g_done;

#define RPB 64   // rows per repack block

__global__ __launch_bounds__(256)
void repack_kernel(const float* __restrict__ emb, int n_classes)
{
    __shared__ float sm[RPB * 50];
    if (blockIdx.x == 0 && threadIdx.x == 0) { g_acc = 0.0; g_done = 0u; }

    int r0 = blockIdx.x * RPB;
    int nrows = n_classes - r0;
    if (nrows > RPB) nrows = RPB;
    int nflt = nrows * 50;

    // r0 multiple of 64 -> byte offset r0*200 is 128B-aligned; stage coalesced.
    const float4* s4 = (const float4*)(emb + (size_t)r0 * 50);
    float4* d4 = (float4*)sm;
    int n4 = nflt >> 2;
    for (int i = threadIdx.x; i < n4; i += 256) d4[i] = s4[i];
    for (int i = (n4 << 2) + threadIdx.x; i < nflt; i += 256) sm[i] = s4[0].x * 0.0f + ((const float*)s4)[i];
    __syncthreads();

    int g = threadIdx.x & 7;
    // each thread serves rows lr and lr+32 within the block
#pragma unroll
    for (int half = 0; half < 2; half++) {
        int lr = (threadIdx.x >> 3) + half * 32;
        bool live = (lr < nrows);
        int lre = live ? lr : 0;
        const float* r = sm + lre * 50;

        float2 c1 = *(const float2*)(r + 2 * g);
        float o1x = fabsf(r[25 + 2 * g]);
        float o1y = fabsf(r[26 + 2 * g]);
        float4 out1 = make_float4(c1.x - o1x, c1.x + o1x, c1.y - o1y, c1.y + o1y);
        float part = (2.0f * o1x) * (2.0f * o1y);

        float4 out2 = make_float4(0.f, 0.f, 0.f, 0.f);
        if (g <= 3) {
            float2 c2 = *(const float2*)(r + 16 + 2 * g);
            float o2x = fabsf(r[41 + 2 * g]);
            float o2y = fabsf(r[42 + 2 * g]);
            out2 = make_float4(c2.x - o2x, c2.x + o2x, c2.y - o2y, c2.y + o2y);
            part *= (2.0f * o2x) * (2.0f * o2y);
        } else if (g == 4) {
            float c24 = r[24];
            float o24 = fabsf(r[49]);
            out2.x = c24 - o24;
            out2.y = c24 + o24;
            part *= 2.0f * o24;
        }

        part *= __shfl_xor_sync(0xFFFFFFFFu, part, 1);
        part *= __shfl_xor_sync(0xFFFFFFFFu, part, 2);
        part *= __shfl_xor_sync(0xFFFFFFFFu, part, 4);

        if (g == 4) {
            float s, b;
            if (part == 0.0f)      { s = 0.0f;            b = 0.0f; }
            else if (isinf(part))  { s = 1.0f / 20000.0f; b = 1.0f; }
            else                   { s = 1.0f / part;     b = 1.0f; }
            out2.z = s;
            out2.w = b;
        }

        if (live) {
            float4* out = (float4*)(g_rows + (size_t)(r0 + lr) * 64);
            out[g] = out1;
            if (g <= 4) out[8 + g] = out2;
        }
    }
}

// one pair's partial product / tail values for lane-group g
__device__ __forceinline__ void pair_body(const int2 p, int g, int j2,
                                          float& prod, float& s, float& b)
{
    const float4* A = (const float4*)(g_rows + (size_t)p.x * 64);
    const float4* B = (const float4*)(g_rows + (size_t)p.y * 64);

    float4 a1 = __ldg(A + g);
    float4 b1 = __ldg(B + g);
    float4 a2 = make_float4(0.f, 0.f, 0.f, 0.f);
    float4 b2 = make_float4(0.f, 0.f, 0.f, 0.f);
    if (j2 <= 12) {
        a2 = __ldg(A + j2);
        b2 = __ldg(B + j2);
    }

    float w0 = fminf(a1.y, b1.y) - fmaxf(a1.x, b1.x);
    float w1 = fminf(a1.w, b1.w) - fmaxf(a1.z, b1.z);
    prod = fmaxf(w0, 0.0f) * fmaxf(w1, 0.0f);

    s = 0.0f; b = 0.0f;
    if (j2 < 12) {
        float u0 = fminf(a2.y, b2.y) - fmaxf(a2.x, b2.x);
        float u1 = fminf(a2.w, b2.w) - fmaxf(a2.z, b2.z);
        prod *= fmaxf(u0, 0.0f) * fmaxf(u1, 0.0f);
    } else if (j2 == 12) {
        float u0 = fminf(a2.y, b2.y) - fmaxf(a2.x, b2.x);
        prod *= fmaxf(u0, 0.0f);
        s = a2.z;
        b = a2.w;
    }
}

// 8 lanes per pair, grid-stride, 2 pairs in flight per group per step.
__global__ __launch_bounds__(256)
void pairs_kernel(const int2* __restrict__ nf1, int n_pairs, int n_groups,
                  int n_iter, float* __restrict__ out)
{
    int tid   = blockIdx.x * blockDim.x + threadIdx.x;
    int group = tid >> 3;
    int g     = tid & 7;
    int j2    = g + 8;

    float acc = 0.0f;

    for (int it = 0; it < n_iter; it += 2) {
        int pair0 = group + it * n_groups;
        int pair1 = pair0 + n_groups;
        bool live0 = (pair0 < n_pairs);
        bool live1 = (pair1 < n_pairs);
        int pe0 = live0 ? pair0 : (n_pairs - 1);
        int pe1 = live1 ? pair1 : (n_pairs - 1);

        int2 p0 = __ldg(nf1 + pe0);
        int2 p1 = __ldg(nf1 + pe1);

        float prod0, s0, b0, prod1, s1, b1v;
        pair_body(p0, g, j2, prod0, s0, b0);
        pair_body(p1, g, j2, prod1, s1, b1v);

        prod0 *= __shfl_xor_sync(0xFFFFFFFFu, prod0, 1);
        prod1 *= __shfl_xor_sync(0xFFFFFFFFu, prod1, 1);
        prod0 *= __shfl_xor_sync(0xFFFFFFFFu, prod0, 2);
        prod1 *= __shfl_xor_sync(0xFFFFFFFFu, prod1, 2);
        prod0 *= __shfl_xor_sync(0xFFFFFFFFu, prod0, 4);
        prod1 *= __shfl_xor_sync(0xFFFFFFFFu, prod1, 4);

        if (g == 4) {
            if (live0) {
                float loss = b0 - prod0 * s0;
                float rl = fmaxf(loss, 0.0f);
                acc += rl * rl;
            }
            if (live1) {
                float loss = b1v - prod1 * s1;
                float rl = fmaxf(loss, 0.0f);
                acc += rl * rl;
            }
        }
    }

    // warp reduce
#pragma unroll
    for (int off = 16; off > 0; off >>= 1)
        acc += __shfl_down_sync(0xFFFFFFFFu, acc, off);

    __shared__ float smred[8];
    int lane = threadIdx.x & 31;
    int wid  = threadIdx.x >> 5;
    if (lane == 0) smred[wid] = acc;
    __syncthreads();
    if (wid == 0) {
        float v = (lane < 8) ? smred[lane] : 0.0f;
#pragma unroll
        for (int off = 4; off > 0; off >>= 1)
            v += __shfl_down_sync(0xFFFFFFFFu, v, off);
        if (lane == 0) {
            atomicAdd(&g_acc, (double)v);
            __threadfence();
            unsigned int old = atomicAdd(&g_done, 1u);
            if (old == gridDim.x - 1) {
                // all blocks' atomics are visible (they fenced before arriving)
                double total = *((volatile double*)&g_acc);
                out[0] = (float)sqrt(total);
            }
        }
    }
}

extern "C" void kernel_launch(void* const* d_in, const int* in_sizes, int n_in,
                              void* d_out, int out_size)
{
    const float* class_embeds = (const float*)d_in[0];
    const int2*  nf1          = (const int2*)d_in[1];
    int n_classes = in_sizes[0] / 50;
    int n_pairs   = in_sizes[1] / 2;

    repack_kernel<<<(n_classes + RPB - 1) / RPB, 256>>>(class_embeds, n_classes);

    {
        const int grid = 2368;
        const int n_groups = grid * 256 / 8;
        int n_iter = (n_pairs + n_groups - 1) / n_groups;
        if (n_iter & 1) n_iter++;   // loop steps by 2
        pairs_kernel<<<grid, 256>>>(nf1, n_pairs, n_groups, n_iter, (float*)d_out);
    }
}

// round 5
// speedup vs baseline: 1.0747x; 1.0747x over previous
#include <cuda_runtime.h>
#include <math.h>

// Repacked class boxes. Row = 64 floats (256B, line-aligned).
// f[2k]=lo_k, f[2k+1]=hi_k (k=0..24); f[50]=s; f[51]=b; rest pad.
// loss = b - inter_area * s reproduces the reference's 3-way where().
#define MAX_CLASSES 100000
__device__ float g_rows[(size_t)MAX_CLASSES * 64];
__device__ double g_acc;
__device__ unsigned int g_done;

#define RPB 64   // rows per repack block

__global__ __launch_bounds__(256)
void repack_kernel(const float* __restrict__ emb, int n_classes)
{
    __shared__ float sm[RPB * 50];
    if (blockIdx.x == 0 && threadIdx.x == 0) { g_acc = 0.0; g_done = 0u; }

    int r0 = blockIdx.x * RPB;
    int nrows = n_classes - r0;
    if (nrows > RPB) nrows = RPB;
    int nflt = nrows * 50;

    // r0 multiple of 64 -> byte offset r0*200 is 128B-aligned; stage coalesced.
    const float4* s4 = (const float4*)(emb + (size_t)r0 * 50);
    float4* d4 = (float4*)sm;
    int n4 = nflt >> 2;
    for (int i = threadIdx.x; i < n4; i += 256) d4[i] = s4[i];
    for (int i = (n4 << 2) + threadIdx.x; i < nflt; i += 256)
        sm[i] = ((const float*)s4)[i];
    __syncthreads();

    int g = threadIdx.x & 7;
#pragma unroll
    for (int half = 0; half < 2; half++) {
        int lr = (threadIdx.x >> 3) + half * 32;
        bool live = (lr < nrows);
        int lre = live ? lr : 0;
        const float* r = sm + lre * 50;

        float2 c1 = *(const float2*)(r + 2 * g);
        float o1x = fabsf(r[25 + 2 * g]);
        float o1y = fabsf(r[26 + 2 * g]);
        float4 out1 = make_float4(c1.x - o1x, c1.x + o1x, c1.y - o1y, c1.y + o1y);
        float part = (2.0f * o1x) * (2.0f * o1y);

        float4 out2 = make_float4(0.f, 0.f, 0.f, 0.f);
        if (g <= 3) {
            float2 c2 = *(const float2*)(r + 16 + 2 * g);
            float o2x = fabsf(r[41 + 2 * g]);
            float o2y = fabsf(r[42 + 2 * g]);
            out2 = make_float4(c2.x - o2x, c2.x + o2x, c2.y - o2y, c2.y + o2y);
            part *= (2.0f * o2x) * (2.0f * o2y);
        } else if (g == 4) {
            float c24 = r[24];
            float o24 = fabsf(r[49]);
            out2.x = c24 - o24;
            out2.y = c24 + o24;
            part *= 2.0f * o24;
        }

        part *= __shfl_xor_sync(0xFFFFFFFFu, part, 1);
        part *= __shfl_xor_sync(0xFFFFFFFFu, part, 2);
        part *= __shfl_xor_sync(0xFFFFFFFFu, part, 4);

        if (g == 4) {
            float s, b;
            if (part == 0.0f)      { s = 0.0f;            b = 0.0f; }
            else if (isinf(part))  { s = 1.0f / 20000.0f; b = 1.0f; }
            else                   { s = 1.0f / part;     b = 1.0f; }
            out2.z = s;
            out2.w = b;
        }

        if (live) {
            float4* out = (float4*)(g_rows + (size_t)(r0 + lr) * 64);
            out[g] = out1;
            if (g <= 4) out[8 + g] = out2;
        }
    }
}

// 8 lanes per pair, grid-stride, single pair per step, next-index prefetched.
__global__ __launch_bounds__(256)
void pairs_kernel(const int2* __restrict__ nf1, int n_pairs, int n_groups,
                  int n_iter, float* __restrict__ out)
{
    int tid   = blockIdx.x * blockDim.x + threadIdx.x;
    int group = tid >> 3;
    int g     = tid & 7;
    int j2    = g + 8;

    float acc = 0.0f;
    int pair = group;
    int pe = (pair < n_pairs) ? pair : (n_pairs - 1);
    int2 p = __ldg(nf1 + pe);

    for (int it = 0; it < n_iter; it++) {
        bool live = (pair < n_pairs);
        int next = pair + n_groups;

        // prefetch next iteration's indices (1 extra load in flight only)
        int2 pn = p;
        if (it + 1 < n_iter) {
            int ne = (next < n_pairs) ? next : (n_pairs - 1);
            pn = __ldg(nf1 + ne);
        }

        const float4* A = (const float4*)(g_rows + (size_t)p.x * 64);
        const float4* B = (const float4*)(g_rows + (size_t)p.y * 64);

        float4 a1 = __ldg(A + g);
        float4 b1 = __ldg(B + g);
        float w0 = fminf(a1.y, b1.y) - fmaxf(a1.x, b1.x);
        float w1 = fminf(a1.w, b1.w) - fmaxf(a1.z, b1.z);
        float prod = fmaxf(w0, 0.0f) * fmaxf(w1, 0.0f);

        float s = 0.0f, b = 0.0f;
        if (j2 <= 12) {
            float4 a2 = __ldg(A + j2);
            float4 b2 = __ldg(B + j2);
            if (j2 < 12) {
                float u0 = fminf(a2.y, b2.y) - fmaxf(a2.x, b2.x);
                float u1 = fminf(a2.w, b2.w) - fmaxf(a2.z, b2.z);
                prod *= fmaxf(u0, 0.0f) * fmaxf(u1, 0.0f);
            } else {
                float u0 = fminf(a2.y, b2.y) - fmaxf(a2.x, b2.x);
                prod *= fmaxf(u0, 0.0f);
                s = a2.z;   // 1/area (or 1/20000, or 0)
                b = a2.w;   // 1 (or 0)
            }
        }

        prod *= __shfl_xor_sync(0xFFFFFFFFu, prod, 1);
        prod *= __shfl_xor_sync(0xFFFFFFFFu, prod, 2);
        prod *= __shfl_xor_sync(0xFFFFFFFFu, prod, 4);

        if (g == 4 && live) {
            float loss = b - prod * s;
            float rl = fmaxf(loss, 0.0f);
            acc += rl * rl;
        }

        p = pn;
        pair = next;
    }

    // warp reduce
#pragma unroll
    for (int off = 16; off > 0; off >>= 1)
        acc += __shfl_down_sync(0xFFFFFFFFu, acc, off);

    __shared__ float smred[8];
    int lane = threadIdx.x & 31;
    int wid  = threadIdx.x >> 5;
    if (lane == 0) smred[wid] = acc;
    __syncthreads();
    if (wid == 0) {
        float v = (lane < 8) ? smred[lane] : 0.0f;
#pragma unroll
        for (int off = 4; off > 0; off >>= 1)
            v += __shfl_down_sync(0xFFFFFFFFu, v, off);
        if (lane == 0) {
            atomicAdd(&g_acc, (double)v);
            __threadfence();
            unsigned int old = atomicAdd(&g_done, 1u);
            if (old == gridDim.x - 1) {
                double total = *((volatile double*)&g_acc);
                out[0] = (float)sqrt(total);
            }
        }
    }
}

extern "C" void kernel_launch(void* const* d_in, const int* in_sizes, int n_in,
                              void* d_out, int out_size)
{
    const float* class_embeds = (const float*)d_in[0];
    const int2*  nf1          = (const int2*)d_in[1];
    int n_classes = in_sizes[0] / 50;
    int n_pairs   = in_sizes[1] / 2;

    repack_kernel<<<(n_classes + RPB - 1) / RPB, 256>>>(class_embeds, n_classes);

    {
        const int grid = 1184;              // one fully-resident wave (8 blocks/SM)
        const int n_groups = grid * 256 / 8;
        int n_iter = (n_pairs + n_groups - 1) / n_groups;
        pairs_kernel<<<grid, 256>>>(nf1, n_pairs, n_groups, n_iter, (float*)d_out);
    }
}